// round 13
// baseline (speedup 1.0000x reference)
#include <cuda_runtime.h>

#define NN 1024
#define DD 128
#define NL 3

typedef unsigned long long u64;

// ---------------- f32x2 helpers ----------------
__device__ __forceinline__ u64 pack2(float x, float y){ u64 r; asm("mov.b64 %0,{%1,%2};":"=l"(r):"f"(x),"f"(y)); return r; }
__device__ __forceinline__ u64 dup2(float x){ return pack2(x,x); }
__device__ __forceinline__ u64 fma2(u64 a,u64 b,u64 c){ u64 d; asm("fma.rn.f32x2 %0,%1,%2,%3;":"=l"(d):"l"(a),"l"(b),"l"(c)); return d; }
__device__ __forceinline__ u64 add2(u64 a,u64 b){ u64 d; asm("add.rn.f32x2 %0,%1,%2;":"=l"(d):"l"(a),"l"(b)); return d; }
__device__ __forceinline__ float2 unpk(u64 x){ float2 f; asm("mov.b64 {%0,%1},%2;":"=f"(f.x),"=f"(f.y):"l"(x)); return f; }

// ---------------- scratch ----------------
__device__ float g_h  [NN*DD];
__device__ float g_v  [NN*DD];
__device__ float g_tp [NN*DD];       // tpre = h@Wug + b2
__device__ float g_agg[NN*DD];
__device__ float g_hi [NN*DD];
__device__ float g_hjb[NN*DD];
__device__ float g_P  [8][NN*DD];    // agg split-K partials
__device__ float g_Wug[NL][DD*DD];
__device__ float g_b2 [NL][DD];
__device__ float g_part[256];

// ---------------- shared tiles ----------------
struct SM64 { float As[32][68]; float Bs[32][128]; };   // 25 KB
struct SM32 { float As[32][36]; float Bs[32][128]; };   // 20.6 KB

// ---------------- 64-row x 128-col GEMM core, 4r x 8c per thread ----------------
template<int KLEN>
__device__ __forceinline__ void gemm64_core(SM64& s,
    const float* __restrict__ A, int lda,
    const float* __restrict__ B, u64 acc[4][4])
{
    int t = threadIdx.x;
    int r0 = (t >> 4) * 4;
    int c0 = (t & 15) * 8;
    for (int kb = 0; kb < KLEN; kb += 32){
        __syncthreads();
#pragma unroll
        for (int e = 0; e < 2; e++){              // A: 64r x 32k, transposed
            int idx = e*256 + t;
            int r = idx >> 3, f4 = idx & 7;
            float4 v = *(const float4*)&A[(size_t)r*lda + kb + f4*4];
            s.As[f4*4+0][r]=v.x; s.As[f4*4+1][r]=v.y;
            s.As[f4*4+2][r]=v.z; s.As[f4*4+3][r]=v.w;
        }
#pragma unroll
        for (int e = 0; e < 4; e++){              // B: 32k x 128c
            int idx = e*256 + t;
            int k = idx >> 5, c4 = idx & 31;
            *(float4*)&s.Bs[k][c4*4] = *(const float4*)&B[(size_t)(kb+k)*DD + c4*4];
        }
        __syncthreads();
#pragma unroll 8
        for (int k = 0; k < 32; k++){
            float4 a = *(const float4*)&s.As[k][r0];
            ulonglong2 b0 = *(const ulonglong2*)&s.Bs[k][c0];
            ulonglong2 b1 = *(const ulonglong2*)&s.Bs[k][c0+4];
            u64 d0=dup2(a.x), d1=dup2(a.y), d2=dup2(a.z), d3=dup2(a.w);
            acc[0][0]=fma2(d0,b0.x,acc[0][0]); acc[0][1]=fma2(d0,b0.y,acc[0][1]);
            acc[0][2]=fma2(d0,b1.x,acc[0][2]); acc[0][3]=fma2(d0,b1.y,acc[0][3]);
            acc[1][0]=fma2(d1,b0.x,acc[1][0]); acc[1][1]=fma2(d1,b0.y,acc[1][1]);
            acc[1][2]=fma2(d1,b1.x,acc[1][2]); acc[1][3]=fma2(d1,b1.y,acc[1][3]);
            acc[2][0]=fma2(d2,b0.x,acc[2][0]); acc[2][1]=fma2(d2,b0.y,acc[2][1]);
            acc[2][2]=fma2(d2,b1.x,acc[2][2]); acc[2][3]=fma2(d2,b1.y,acc[2][3]);
            acc[3][0]=fma2(d3,b0.x,acc[3][0]); acc[3][1]=fma2(d3,b0.y,acc[3][1]);
            acc[3][2]=fma2(d3,b1.x,acc[3][2]); acc[3][3]=fma2(d3,b1.y,acc[3][3]);
        }
    }
}

__device__ __forceinline__ void store64(u64 acc[4][4], const float* bias,
                                        float* O, int rb)
{
    int t = threadIdx.x;
    int r0 = (t >> 4) * 4;
    int c0 = (t & 15) * 8;
    u64 bb[4] = {0ull,0ull,0ull,0ull};
    if (bias){
        float4 x = *(const float4*)&bias[c0];
        float4 y = *(const float4*)&bias[c0+4];
        bb[0]=pack2(x.x,x.y); bb[1]=pack2(x.z,x.w);
        bb[2]=pack2(y.x,y.y); bb[3]=pack2(y.z,y.w);
    }
#pragma unroll
    for (int r = 0; r < 4; r++){
        float* dst = O + (size_t)(rb + r0 + r)*DD + c0;
        ulonglong2 s1, s2;
        s1.x = add2(acc[r][0], bb[0]); s1.y = add2(acc[r][1], bb[1]);
        s2.x = add2(acc[r][2], bb[2]); s2.y = add2(acc[r][3], bb[3]);
        *(ulonglong2*)dst       = s1;
        *(ulonglong2*)(dst + 4) = s2;
    }
}

// ---------------- embed ----------------
__global__ void embed_kernel(const float* __restrict__ nf,
                             const float* __restrict__ We,
                             const float* __restrict__ be){
    int idx = blockIdx.x * blockDim.x + threadIdx.x;
    int i = idx >> 7, d = idx & 127;
    float a0 = nf[3*i], a1 = nf[3*i+1], a2 = nf[3*i+2];
    g_h[idx] = be[d] + a0*We[d] + a1*We[DD+d] + a2*We[2*DD+d];
}

// ---------------- fold: Wug[l] = Wu[l] @ Wg1[l] ----------------
__global__ __launch_bounds__(256) void fold_kernel(
    const float* __restrict__ Wu, const float* __restrict__ Wg){
    __shared__ SM64 s;
    int l = blockIdx.y, rb = blockIdx.x * 64;
    u64 acc[4][4] = {};
    gemm64_core<DD>(s, Wu + (size_t)l*DD*DD + rb*DD, DD,
                    Wg + (size_t)l*2*DD*DD, acc);
    store64(acc, nullptr, g_Wug[l], rb);
}

// ---------------- b2[l] = bu[l]@Wg1[l] + bg[l] ----------------
__global__ void b2_kernel(const float* __restrict__ bu,
                          const float* __restrict__ Wg,
                          const float* __restrict__ bg){
    int l = blockIdx.x, t = threadIdx.x;
    float acc = 0.f;
    const float* bl = bu + l*DD;
    const float* w  = Wg + (size_t)l*2*DD*DD;
#pragma unroll 4
    for (int d = 0; d < DD; d++) acc = fmaf(bl[d], w[(size_t)d*DD + t], acc);
    g_b2[l][t] = acc + bg[l*DD + t];
}

// ---------------- dual GEMM from g_h: (O1=h@B1+b1, O2=h@B2+b2). grid (16,2) ----------------
__global__ __launch_bounds__(256) void dual_kernel(
    const float* __restrict__ B1, const float* __restrict__ B2,
    const float* __restrict__ bias1, const float* __restrict__ bias2,
    float* __restrict__ O1, float* __restrict__ O2){
    __shared__ SM64 s;
    int rb = blockIdx.x * 64;
    const float* B    = blockIdx.y ? B2    : B1;
    const float* bias = blockIdx.y ? bias2 : bias1;
    float*       O    = blockIdx.y ? O2    : O1;
    u64 acc[4][4] = {};
    gemm64_core<DD>(s, g_h + (size_t)rb*DD, DD, B, acc);
    store64(acc, bias, O, rb);
}

// ---------------- agg partials: P[ks] = adj[:,ks*128:+128] @ v[ks*128:+128,:]. grid (16,8) ----
__global__ __launch_bounds__(256) void agg_kernel(const float* __restrict__ adj){
    __shared__ SM64 s;
    int rb = blockIdx.x * 64, ks = blockIdx.y, kst = ks * 128;
    u64 acc[4][4] = {};
    gemm64_core<128>(s, adj + (size_t)rb*NN + kst, NN,
                     g_v + (size_t)kst*DD, acc);
    store64(acc, nullptr, g_P[ks], rb);
}

// ---------------- gate finish: agg=sum P; t=tpre+agg@Wg2; h=relu(h+sig(t)*agg). grid 32 ----
__global__ __launch_bounds__(256) void gatefin_kernel(
    const float* __restrict__ Wg2, const float* __restrict__ bgl){
    __shared__ SM32 s;
    int t = threadIdx.x, rb = blockIdx.x * 32;
    int r0 = (t >> 4) * 2, c0 = (t & 15) * 8;
    u64 acc[2][4] = {};

    for (int kb = 0; kb < DD; kb += 32){
        __syncthreads();
        {   // A: summed slabs, 32r x 32k transposed; also persist agg
            int r = t >> 3, f4 = t & 7;
            size_t off = (size_t)(rb + r)*DD + kb + f4*4;
            float4 v = *(const float4*)&g_P[0][off];
#pragma unroll
            for (int z = 1; z < 8; z++){
                float4 p = *(const float4*)&g_P[z][off];
                v.x+=p.x; v.y+=p.y; v.z+=p.z; v.w+=p.w;
            }
            *(float4*)&g_agg[off] = v;
            s.As[f4*4+0][r]=v.x; s.As[f4*4+1][r]=v.y;
            s.As[f4*4+2][r]=v.z; s.As[f4*4+3][r]=v.w;
        }
#pragma unroll
        for (int e = 0; e < 4; e++){
            int idx = e*256 + t;
            int k = idx >> 5, c4 = idx & 31;
            *(float4*)&s.Bs[k][c4*4] = *(const float4*)&Wg2[(size_t)(kb+k)*DD + c4*4];
        }
        __syncthreads();
#pragma unroll 8
        for (int k = 0; k < 32; k++){
            float2 a = *(const float2*)&s.As[k][r0];
            ulonglong2 b0 = *(const ulonglong2*)&s.Bs[k][c0];
            ulonglong2 b1 = *(const ulonglong2*)&s.Bs[k][c0+4];
            u64 d0=dup2(a.x), d1=dup2(a.y);
            acc[0][0]=fma2(d0,b0.x,acc[0][0]); acc[0][1]=fma2(d0,b0.y,acc[0][1]);
            acc[0][2]=fma2(d0,b1.x,acc[0][2]); acc[0][3]=fma2(d0,b1.y,acc[0][3]);
            acc[1][0]=fma2(d1,b0.x,acc[1][0]); acc[1][1]=fma2(d1,b0.y,acc[1][1]);
            acc[1][2]=fma2(d1,b1.x,acc[1][2]); acc[1][3]=fma2(d1,b1.y,acc[1][3]);
        }
    }
    __syncthreads();   // order g_agg writes before epilogue reads (block-local rows)

    float4 bg0 = *(const float4*)&bgl[c0];
    float4 bg1 = *(const float4*)&bgl[c0+4];
    float bga[8] = {bg0.x,bg0.y,bg0.z,bg0.w,bg1.x,bg1.y,bg1.z,bg1.w};
#pragma unroll
    for (int r = 0; r < 2; r++){
        size_t off = (size_t)(rb + r0 + r)*DD + c0;
        float4 tp0 = *(const float4*)&g_tp[off];
        float4 tp1 = *(const float4*)&g_tp[off+4];
        float4 ag0 = *(const float4*)&g_agg[off];
        float4 ag1 = *(const float4*)&g_agg[off+4];
        float4 h0  = *(const float4*)&g_h[off];
        float4 h1  = *(const float4*)&g_h[off+4];
        float tt[8], aa[8] = {ag0.x,ag0.y,ag0.z,ag0.w,ag1.x,ag1.y,ag1.z,ag1.w};
        float hh[8] = {h0.x,h0.y,h0.z,h0.w,h1.x,h1.y,h1.z,h1.w};
        float tpv[8] = {tp0.x,tp0.y,tp0.z,tp0.w,tp1.x,tp1.y,tp1.z,tp1.w};
        float2 p;
        p=unpk(acc[r][0]); tt[0]=p.x; tt[1]=p.y;
        p=unpk(acc[r][1]); tt[2]=p.x; tt[3]=p.y;
        p=unpk(acc[r][2]); tt[4]=p.x; tt[5]=p.y;
        p=unpk(acc[r][3]); tt[6]=p.x; tt[7]=p.y;
        float oo[8];
#pragma unroll
        for (int q = 0; q < 8; q++){
            float tv = tt[q] + tpv[q] + bga[q];
            float g = 1.f/(1.f + __expf(-tv));
            oo[q] = fmaxf(hh[q] + g*aa[q], 0.f);
        }
        *(float4*)&g_h[off]   = make_float4(oo[0],oo[1],oo[2],oo[3]);
        *(float4*)&g_h[off+4] = make_float4(oo[4],oo[5],oo[6],oo[7]);
    }
}

// ---------------- classifier + loss partials (64x64 tiles, grid (16,16)) ----------------
__global__ __launch_bounds__(256, 2) void cls_kernel(
    const float* __restrict__ Wc2, const float* __restrict__ bc2,
    const float* __restrict__ adj, const float* __restrict__ ew,
    float* __restrict__ out)
{
    __shared__ float hiS[64][34];
    __shared__ float hjS[64][34];
    __shared__ u64   wsS[64];
    __shared__ float siS[64], sjS[64];
    __shared__ float red[256];

    int t  = threadIdx.x;
    int ib = blockIdx.y * 64, jb = blockIdx.x * 64;

    if (t < 128){
        const float* row = (t < 64) ? &g_hi[(size_t)(ib + t)*DD]
                                    : &g_hjb[(size_t)(jb + t - 64)*DD];
        float s0=0.f,s1=0.f,s2=0.f,s3=0.f;
#pragma unroll
        for (int h = 0; h < DD; h += 4){
            float4 v = *(const float4*)&row[h];
            float4 w = *(const float4*)&Wc2[h];
            s0=fmaf(v.x,w.x,s0); s1=fmaf(v.y,w.y,s1);
            s2=fmaf(v.z,w.z,s2); s3=fmaf(v.w,w.w,s3);
        }
        float s = 0.5f*((s0+s1)+(s2+s3));
        if (t < 64) siS[t]      = s;
        else        sjS[t - 64] = s + bc2[0];
    } else if (t < 192){
        int h2 = t - 128;
        wsS[h2] = pack2(0.5f*Wc2[2*h2], 0.5f*Wc2[2*h2+1]);
    }

    int ig = t >> 4, jg = t & 15;
    const u64 amask = 0x7FFFFFFF7FFFFFFFull;

    u64 acc[4][4];
#pragma unroll
    for (int a=0;a<4;a++)
#pragma unroll
        for (int b=0;b<4;b++) acc[a][b]=0ull;

    for (int hc = 0; hc < DD; hc += 32){
        __syncthreads();
#pragma unroll
        for (int e=0;e<4;e++){
            int idx=e*256+t;
            int r=idx>>4, q=(idx&15)*2;
            *(float2*)&hiS[r][q] = *(const float2*)&g_hi [(size_t)(ib+r)*DD + hc + q];
            *(float2*)&hjS[r][q] = *(const float2*)&g_hjb[(size_t)(jb+r)*DD + hc + q];
        }
        __syncthreads();
#pragma unroll
        for (int hp=0; hp<16; hp++){
            u64 wp = wsS[(hc>>1)+hp];
            u64 ai[4], bj[4];
#pragma unroll
            for (int a=0;a<4;a++){
                ai[a] = *(const u64*)&hiS[ig + a*16][hp*2];
                bj[a] = *(const u64*)&hjS[jg + a*16][hp*2];
            }
#pragma unroll
            for (int a=0;a<4;a++)
#pragma unroll
                for (int b=0;b<4;b++){
                    u64 s = add2(ai[a], bj[b]) & amask;
                    acc[a][b] = fma2(s, wp, acc[a][b]);
                }
        }
    }

    float lsum = 0.f;
#pragma unroll
    for (int a=0;a<4;a++){
        int i = ib + ig + a*16;
        float sia = siS[ig + a*16];
#pragma unroll
        for (int b=0;b<4;b++){
            int j = jb + jg + b*16;
            float2 p = unpk(acc[a][b]);
            float lg = (p.x + p.y) + sia + sjS[jg + b*16];
            size_t off = (size_t)i*NN + j;
            out[off] = lg;
            float d = lg*adj[off] - ew[off];
            lsum = fmaf(d, d, lsum);
        }
    }

    red[t] = lsum;
    __syncthreads();
#pragma unroll
    for (int s=128; s>0; s>>=1){
        if (t < s) red[t] += red[t+s];
        __syncthreads();
    }
    if (t == 0) g_part[blockIdx.y*16 + blockIdx.x] = red[0];
}

// ---------------- final loss reduce ----------------
__global__ void loss_kernel(float* __restrict__ out_loss){
    __shared__ float red[256];
    int t = threadIdx.x;
    red[t] = g_part[t];
    __syncthreads();
#pragma unroll
    for (int s=128; s>0; s>>=1){
        if (t < s) red[t] += red[t+s];
        __syncthreads();
    }
    if (t == 0) out_loss[0] = red[0] * (1.f/(1024.f*1024.f));
}

// ---------------- launch ----------------
extern "C" void kernel_launch(void* const* d_in, const int* in_sizes, int n_in,
                              void* d_out, int out_size)
{
    const float* nf   = (const float*)d_in[0];
    const float* adj  = (const float*)d_in[1];
    const float* ew   = (const float*)d_in[2];
    const float* We   = (const float*)d_in[3];
    const float* be   = (const float*)d_in[4];
    const float* Wu   = (const float*)d_in[5];
    const float* bu   = (const float*)d_in[6];
    const float* Wv   = (const float*)d_in[7];
    const float* bv   = (const float*)d_in[8];
    const float* Wg   = (const float*)d_in[9];
    const float* bg   = (const float*)d_in[10];
    const float* Wc1  = (const float*)d_in[11];
    const float* bc1  = (const float*)d_in[12];
    const float* Wc2  = (const float*)d_in[13];
    const float* bc2  = (const float*)d_in[14];
    float* out = (float*)d_out;

    float *pv, *ptp, *phi, *phjb, *pWug, *pb2;
    cudaGetSymbolAddress((void**)&pv,   g_v);
    cudaGetSymbolAddress((void**)&ptp,  g_tp);
    cudaGetSymbolAddress((void**)&phi,  g_hi);
    cudaGetSymbolAddress((void**)&phjb, g_hjb);
    cudaGetSymbolAddress((void**)&pWug, g_Wug);
    cudaGetSymbolAddress((void**)&pb2,  g_b2);

    embed_kernel<<<NN*DD/256, 256>>>(nf, We, be);
    fold_kernel<<<dim3(2, NL), 256>>>(Wu, Wg);
    b2_kernel<<<NL, DD>>>(bu, Wg, bg);

    for (int l = 0; l < NL; l++){
        dual_kernel<<<dim3(16, 2), 256>>>(Wv + (size_t)l*DD*DD, pWug + (size_t)l*DD*DD,
                                          bv + l*DD, pb2 + l*DD,
                                          pv, ptp);
        agg_kernel<<<dim3(16, 8), 256>>>(adj);
        gatefin_kernel<<<32, 256>>>(Wg + (size_t)l*2*DD*DD + DD*DD, bg + l*DD);
    }

    dual_kernel<<<dim3(16, 2), 256>>>(Wc1, Wc1 + DD*DD,
                                      nullptr, bc1,
                                      phi, phjb);

    cls_kernel<<<dim3(16, 16), 256>>>(Wc2, bc2, adj, ew, out);

    if (out_size > NN*NN){
        loss_kernel<<<1, 256>>>(out + NN*NN);
    }
}

// round 14
// speedup vs baseline: 2.1815x; 2.1815x over previous
#include <cuda_runtime.h>

#define NN 1024
#define DD 128
#define NL 3

typedef unsigned long long u64;

// ---------------- f32x2 helpers ----------------
__device__ __forceinline__ u64 pack2(float x, float y){ u64 r; asm("mov.b64 %0,{%1,%2};":"=l"(r):"f"(x),"f"(y)); return r; }
__device__ __forceinline__ u64 dup2(float x){ return pack2(x,x); }
__device__ __forceinline__ u64 fma2(u64 a,u64 b,u64 c){ u64 d; asm("fma.rn.f32x2 %0,%1,%2,%3;":"=l"(d):"l"(a),"l"(b),"l"(c)); return d; }
__device__ __forceinline__ u64 add2(u64 a,u64 b){ u64 d; asm("add.rn.f32x2 %0,%1,%2;":"=l"(d):"l"(a),"l"(b)); return d; }
__device__ __forceinline__ float2 unpk(u64 x){ float2 f; asm("mov.b64 {%0,%1},%2;":"=f"(f.x),"=f"(f.y):"l"(x)); return f; }

// ---------------- scratch ----------------
__device__ float g_h  [NN*DD];
__device__ float g_v  [NN*DD];
__device__ float g_tp [NN*DD];       // tpre = h@Wug + b2   (b2 = bu@Wg1 + bg)
__device__ float g_hi [NN*DD];
__device__ float g_hjb[NN*DD];
__device__ float g_P  [4][NN*DD];    // agg split-K partials
__device__ float g_Wug[NL][DD*DD];
__device__ float g_b2 [NL][DD];
__device__ float g_part[256];

// ---------------- embed: h = nf @ We + be ----------------
__global__ void embed_kernel(const float* __restrict__ nf,
                             const float* __restrict__ We,
                             const float* __restrict__ be) {
    int idx = blockIdx.x * blockDim.x + threadIdx.x;
    int i = idx >> 7, d = idx & 127;
    float a0 = nf[3*i], a1 = nf[3*i+1], a2 = nf[3*i+2];
    g_h[idx] = be[d] + a0*We[d] + a1*We[DD + d] + a2*We[2*DD + d];
}

// ---------------- 16-row x 128-col GEMM core, K=128, 2r x 4c per thread ----------------
struct SMn { float As[32][18]; float Bs[32][128]; };

__device__ __forceinline__ void gemm16_core(SMn& s,
    const float* __restrict__ A,           // 16 rows, lda = DD
    const float* __restrict__ B,           // [128][128]
    u64 acc[2][2])
{
    int t = threadIdx.x;
    int r0 = (t >> 5) * 2;                 // warp-uniform -> broadcast LDS
    int c0 = (t & 31) * 4;
    for (int kb = 0; kb < DD; kb += 32){
        __syncthreads();
        if (t < 128){
            int r = t >> 3, f4 = t & 7;
            float4 v = *(const float4*)&A[(size_t)r*DD + kb + f4*4];
            s.As[f4*4+0][r]=v.x; s.As[f4*4+1][r]=v.y;
            s.As[f4*4+2][r]=v.z; s.As[f4*4+3][r]=v.w;
        }
#pragma unroll
        for (int e = 0; e < 4; e++){
            int idx = e*256 + t;
            int k = idx >> 5, c4 = idx & 31;
            *(float4*)&s.Bs[k][c4*4] = *(const float4*)&B[(size_t)(kb+k)*DD + c4*4];
        }
        __syncthreads();
#pragma unroll
        for (int k = 0; k < 32; k++){
            float2 a2 = *(const float2*)&s.As[k][r0];
            ulonglong2 b = *(const ulonglong2*)&s.Bs[k][c0];
            u64 d0 = dup2(a2.x), d1 = dup2(a2.y);
            acc[0][0]=fma2(d0,b.x,acc[0][0]); acc[0][1]=fma2(d0,b.y,acc[0][1]);
            acc[1][0]=fma2(d1,b.x,acc[1][0]); acc[1][1]=fma2(d1,b.y,acc[1][1]);
        }
    }
}

__device__ __forceinline__ void store16(u64 acc[2][2], const float* bias,
                                        float* O)     // O at row 0 of tile
{
    int t = threadIdx.x;
    int r0 = (t >> 5) * 2;
    int c0 = (t & 31) * 4;
    u64 bb0 = 0ull, bb1 = 0ull;
    if (bias){
        float4 u = *(const float4*)&bias[c0];
        bb0 = pack2(u.x, u.y); bb1 = pack2(u.z, u.w);
    }
    ulonglong2 s;
    s.x = add2(acc[0][0], bb0); s.y = add2(acc[0][1], bb1);
    *(ulonglong2*)&O[(size_t)r0*DD + c0] = s;
    s.x = add2(acc[1][0], bb0); s.y = add2(acc[1][1], bb1);
    *(ulonglong2*)&O[(size_t)(r0+1)*DD + c0] = s;
}

// ---------------- dual GEMM from g_h: grid (64, 2) ----------------
__global__ __launch_bounds__(256, 4) void dual_kernel(
    const float* __restrict__ B1, const float* __restrict__ B2,
    const float* __restrict__ bias1, const float* __restrict__ bias2,
    float* __restrict__ O1, float* __restrict__ O2)
{
    __shared__ SMn s;
    int rb = blockIdx.x * 16;
    const float* B    = blockIdx.y ? B2    : B1;
    const float* bias = blockIdx.y ? bias2 : bias1;
    float*       O    = blockIdx.y ? O2    : O1;
    u64 acc[2][2] = {};
    gemm16_core(s, g_h + (size_t)rb*DD, B, acc);
    store16(acc, bias, O + (size_t)rb*DD);
}

// ---------------- fold: Wug[l] = Wu[l] @ Wg1[l]. grid (8, NL) ----------------
__global__ __launch_bounds__(256, 4) void fold_kernel(
    const float* __restrict__ Wu, const float* __restrict__ Wg)
{
    __shared__ SMn s;
    int l = blockIdx.y, rb = blockIdx.x * 16;
    u64 acc[2][2] = {};
    gemm16_core(s, Wu + (size_t)l*DD*DD + rb*DD, Wg + (size_t)l*2*DD*DD, acc);
    store16(acc, nullptr, g_Wug[l] + (size_t)rb*DD);
}

// ---------------- b2[l] = bu[l]@Wg1[l] + bg[l]. grid NL x 128 ----------------
__global__ void b2_kernel(const float* __restrict__ bu,
                          const float* __restrict__ Wg,
                          const float* __restrict__ bg)
{
    int l = blockIdx.x, t = threadIdx.x;
    float acc = 0.f;
    const float* bl = bu + l*DD;
    const float* w  = Wg + (size_t)l*2*DD*DD;
#pragma unroll 4
    for (int d = 0; d < DD; d++) acc = fmaf(bl[d], w[(size_t)d*DD + t], acc);
    g_b2[l][t] = acc + bg[l*DD + t];
}

// ---------------- agg partials: P[z] = adj[:, z*256:+256] @ v. grid (32,1,4) ----------------
__global__ __launch_bounds__(256, 2) void agg_gemm_kernel(const float* __restrict__ adj)
{
    __shared__ float As[32][36];     // [k][row]
    __shared__ float Bs[32][128];

    int t  = threadIdx.x;
    int rb = blockIdx.x * 32;
    int kstart = blockIdx.z * 256;

    int r0 = (t >> 5) * 4;           // warp-uniform
    int c0 = (t & 31) * 4;

    u64 acc[4][2];
#pragma unroll
    for (int r = 0; r < 4; r++){ acc[r][0] = 0ull; acc[r][1] = 0ull; }

    for (int kb = kstart; kb < kstart + 256; kb += 32){
        __syncthreads();
        {
            int r = t >> 3, f4 = t & 7;
            float4 v = *(const float4*)&adj[(size_t)(rb + r)*NN + kb + f4*4];
            As[f4*4+0][r]=v.x; As[f4*4+1][r]=v.y;
            As[f4*4+2][r]=v.z; As[f4*4+3][r]=v.w;
        }
#pragma unroll
        for (int e = 0; e < 4; e++){
            int idx = e*256 + t;
            int k = idx >> 5, c4 = idx & 31;
            *(float4*)&Bs[k][c4*4] = *(const float4*)&g_v[(size_t)(kb + k)*DD + c4*4];
        }
        __syncthreads();
#pragma unroll
        for (int k = 0; k < 32; k++){
            float4 a4 = *(const float4*)&As[k][r0];
            ulonglong2 b = *(const ulonglong2*)&Bs[k][c0];
            u64 d0=dup2(a4.x), d1=dup2(a4.y), d2=dup2(a4.z), d3=dup2(a4.w);
            acc[0][0] = fma2(d0, b.x, acc[0][0]); acc[0][1] = fma2(d0, b.y, acc[0][1]);
            acc[1][0] = fma2(d1, b.x, acc[1][0]); acc[1][1] = fma2(d1, b.y, acc[1][1]);
            acc[2][0] = fma2(d2, b.x, acc[2][0]); acc[2][1] = fma2(d2, b.y, acc[2][1]);
            acc[3][0] = fma2(d3, b.x, acc[3][0]); acc[3][1] = fma2(d3, b.y, acc[3][1]);
        }
    }

    float* P = &g_P[blockIdx.z][(size_t)(rb + r0)*DD + c0];
#pragma unroll
    for (int r = 0; r < 4; r++){
        ulonglong2 s2; s2.x = acc[r][0]; s2.y = acc[r][1];
        *(ulonglong2*)(P + (size_t)r*DD) = s2;
    }
}

// ---------------- gate finish: agg = sum P; t = tpre + agg@Wg2;
//                  h = relu(h + sigmoid(t)*agg).  grid 64 (16 rows per block) ----------------
__global__ __launch_bounds__(256, 2) void gatefin_kernel(const float* __restrict__ Wg2)
{
    __shared__ float AsT[DD][18];    // [k][r] summed agg, transposed
    __shared__ float Bs[32][128];

    int t = threadIdx.x;
    int rb = blockIdx.x * 16;

    // slab-sum 4 partials into AsT (16 rows x 128 cols)
#pragma unroll
    for (int e = 0; e < 2; e++){
        int idx = e*256 + t;                 // 512 float4
        int r = idx >> 5, c4 = idx & 31;
        size_t off = (size_t)(rb + r)*DD + c4*4;
        float4 p0 = *(const float4*)&g_P[0][off];
        float4 p1 = *(const float4*)&g_P[1][off];
        float4 p2 = *(const float4*)&g_P[2][off];
        float4 p3 = *(const float4*)&g_P[3][off];
        float4 sv;
        sv.x = (p0.x + p1.x) + (p2.x + p3.x);
        sv.y = (p0.y + p1.y) + (p2.y + p3.y);
        sv.z = (p0.z + p1.z) + (p2.z + p3.z);
        sv.w = (p0.w + p1.w) + (p2.w + p3.w);
        AsT[c4*4+0][r]=sv.x; AsT[c4*4+1][r]=sv.y;
        AsT[c4*4+2][r]=sv.z; AsT[c4*4+3][r]=sv.w;
    }

    int rr = t >> 4;                 // 0..15, one row per 16-thread group
    int c0 = (t & 15) * 8;
    u64 acc[4] = {0ull,0ull,0ull,0ull};

    for (int kb = 0; kb < DD; kb += 32){
        __syncthreads();             // first pass: also covers AsT staging
#pragma unroll
        for (int e = 0; e < 4; e++){
            int idx = e*256 + t;
            int k = idx >> 5, c4 = idx & 31;
            *(float4*)&Bs[k][c4*4] = *(const float4*)&Wg2[(size_t)(kb+k)*DD + c4*4];
        }
        __syncthreads();
#pragma unroll
        for (int k = 0; k < 32; k++){
            u64 d = dup2(AsT[kb + k][rr]);
            ulonglong2 b0 = *(const ulonglong2*)&Bs[k][c0];
            ulonglong2 b1 = *(const ulonglong2*)&Bs[k][c0+4];
            acc[0] = fma2(d, b0.x, acc[0]); acc[1] = fma2(d, b0.y, acc[1]);
            acc[2] = fma2(d, b1.x, acc[2]); acc[3] = fma2(d, b1.y, acc[3]);
        }
    }

    // epilogue: t = acc + tpre (b2 already inside tpre: NO extra bias here)
    {
        size_t off = (size_t)(rb + rr)*DD + c0;
        float4 tp0 = *(const float4*)&g_tp[off];
        float4 tp1 = *(const float4*)&g_tp[off+4];
        float4 h0  = *(const float4*)&g_h[off];
        float4 h1  = *(const float4*)&g_h[off+4];
        float tpv[8] = {tp0.x,tp0.y,tp0.z,tp0.w,tp1.x,tp1.y,tp1.z,tp1.w};
        float hh [8] = {h0.x,h0.y,h0.z,h0.w,h1.x,h1.y,h1.z,h1.w};
        float tt[8];
        float2 p;
        p=unpk(acc[0]); tt[0]=p.x; tt[1]=p.y;
        p=unpk(acc[1]); tt[2]=p.x; tt[3]=p.y;
        p=unpk(acc[2]); tt[4]=p.x; tt[5]=p.y;
        p=unpk(acc[3]); tt[6]=p.x; tt[7]=p.y;
        float oo[8];
#pragma unroll
        for (int q = 0; q < 8; q++){
            float ag = AsT[c0 + q][rr];
            float tv = tt[q] + tpv[q];
            float g  = 1.f / (1.f + __expf(-tv));
            oo[q] = fmaxf(hh[q] + g*ag, 0.f);
        }
        *(float4*)&g_h[off]   = make_float4(oo[0],oo[1],oo[2],oo[3]);
        *(float4*)&g_h[off+4] = make_float4(oo[4],oo[5],oo[6],oo[7]);
    }
}

// ---------------- classifier + loss partials (64x64 tiles, grid (16,16)) ----------------
__global__ __launch_bounds__(256, 2) void cls_kernel(
    const float* __restrict__ Wc2, const float* __restrict__ bc2,
    const float* __restrict__ adj, const float* __restrict__ ew,
    float* __restrict__ out)
{
    __shared__ float hiS[64][34];
    __shared__ float hjS[64][34];
    __shared__ u64   wsS[64];
    __shared__ float siS[64], sjS[64];
    __shared__ float red[256];

    int t  = threadIdx.x;
    int ib = blockIdx.y * 64, jb = blockIdx.x * 64;

    if (t < 128){
        const float* row = (t < 64) ? &g_hi[(size_t)(ib + t)*DD]
                                    : &g_hjb[(size_t)(jb + t - 64)*DD];
        float s0=0.f,s1=0.f,s2=0.f,s3=0.f;
#pragma unroll
        for (int h = 0; h < DD; h += 4){
            float4 v = *(const float4*)&row[h];
            float4 w = *(const float4*)&Wc2[h];
            s0=fmaf(v.x,w.x,s0); s1=fmaf(v.y,w.y,s1);
            s2=fmaf(v.z,w.z,s2); s3=fmaf(v.w,w.w,s3);
        }
        float s = 0.5f*((s0+s1)+(s2+s3));
        if (t < 64) siS[t]      = s;
        else        sjS[t - 64] = s + bc2[0];
    } else if (t < 192){
        int h2 = t - 128;
        wsS[h2] = pack2(0.5f*Wc2[2*h2], 0.5f*Wc2[2*h2+1]);
    }

    int ig = t >> 4, jg = t & 15;
    const u64 amask = 0x7FFFFFFF7FFFFFFFull;

    u64 acc[4][4];
#pragma unroll
    for (int a=0;a<4;a++)
#pragma unroll
        for (int b=0;b<4;b++) acc[a][b]=0ull;

    for (int hc = 0; hc < DD; hc += 32){
        __syncthreads();
#pragma unroll
        for (int e=0;e<4;e++){
            int idx=e*256+t;
            int r=idx>>4, q=(idx&15)*2;
            *(float2*)&hiS[r][q] = *(const float2*)&g_hi [(size_t)(ib+r)*DD + hc + q];
            *(float2*)&hjS[r][q] = *(const float2*)&g_hjb[(size_t)(jb+r)*DD + hc + q];
        }
        __syncthreads();
#pragma unroll
        for (int hp=0; hp<16; hp++){
            u64 wp = wsS[(hc>>1)+hp];
            u64 ai[4], bj[4];
#pragma unroll
            for (int a=0;a<4;a++){
                ai[a] = *(const u64*)&hiS[ig + a*16][hp*2];
                bj[a] = *(const u64*)&hjS[jg + a*16][hp*2];
            }
#pragma unroll
            for (int a=0;a<4;a++)
#pragma unroll
                for (int b=0;b<4;b++){
                    u64 s = add2(ai[a], bj[b]) & amask;
                    acc[a][b] = fma2(s, wp, acc[a][b]);
                }
        }
    }

    float lsum = 0.f;
#pragma unroll
    for (int a=0;a<4;a++){
        int i = ib + ig + a*16;
        float sia = siS[ig + a*16];
#pragma unroll
        for (int b=0;b<4;b++){
            int j = jb + jg + b*16;
            float2 p = unpk(acc[a][b]);
            float lg = (p.x + p.y) + sia + sjS[jg + b*16];
            size_t off = (size_t)i*NN + j;
            out[off] = lg;
            float d = lg*adj[off] - ew[off];
            lsum = fmaf(d, d, lsum);
        }
    }

    red[t] = lsum;
    __syncthreads();
#pragma unroll
    for (int s=128; s>0; s>>=1){
        if (t < s) red[t] += red[t+s];
        __syncthreads();
    }
    if (t == 0) g_part[blockIdx.y*16 + blockIdx.x] = red[0];
}

// ---------------- final loss reduce ----------------
__global__ void loss_kernel(float* __restrict__ out_loss){
    __shared__ float red[256];
    int t = threadIdx.x;
    red[t] = g_part[t];
    __syncthreads();
#pragma unroll
    for (int s=128; s>0; s>>=1){
        if (t < s) red[t] += red[t+s];
        __syncthreads();
    }
    if (t == 0) out_loss[0] = red[0] * (1.f/(1024.f*1024.f));
}

// ---------------- launch ----------------
extern "C" void kernel_launch(void* const* d_in, const int* in_sizes, int n_in,
                              void* d_out, int out_size)
{
    const float* nf   = (const float*)d_in[0];
    const float* adj  = (const float*)d_in[1];
    const float* ew   = (const float*)d_in[2];
    const float* We   = (const float*)d_in[3];
    const float* be   = (const float*)d_in[4];
    const float* Wu   = (const float*)d_in[5];
    const float* bu   = (const float*)d_in[6];
    const float* Wv   = (const float*)d_in[7];
    const float* bv   = (const float*)d_in[8];
    const float* Wg   = (const float*)d_in[9];
    const float* bg   = (const float*)d_in[10];
    const float* Wc1  = (const float*)d_in[11];
    const float* bc1  = (const float*)d_in[12];
    const float* Wc2  = (const float*)d_in[13];
    const float* bc2  = (const float*)d_in[14];
    float* out = (float*)d_out;

    float *pv, *ptp, *phi, *phjb, *pWug, *pb2;
    cudaGetSymbolAddress((void**)&pv,   g_v);
    cudaGetSymbolAddress((void**)&ptp,  g_tp);
    cudaGetSymbolAddress((void**)&phi,  g_hi);
    cudaGetSymbolAddress((void**)&phjb, g_hjb);
    cudaGetSymbolAddress((void**)&pWug, g_Wug);
    cudaGetSymbolAddress((void**)&pb2,  g_b2);

    embed_kernel<<<NN*DD/256, 256>>>(nf, We, be);
    fold_kernel<<<dim3(8, NL), 256>>>(Wu, Wg);
    b2_kernel<<<NL, DD>>>(bu, Wg, bg);

    for (int l = 0; l < NL; l++){
        // v = h@Wv + bv ; tpre = h@Wug + b2
        dual_kernel<<<dim3(64, 2), 256>>>(Wv + (size_t)l*DD*DD, pWug + (size_t)l*DD*DD,
                                          bv + l*DD, pb2 + l*DD,
                                          pv, ptp);
        agg_gemm_kernel<<<dim3(32, 1, 4), 256>>>(adj);
        gatefin_kernel<<<64, 256>>>(Wg + (size_t)l*2*DD*DD + DD*DD);
    }

    // hi = h@Wc1[:D] ; hjb = h@Wc1[D:] + bc1
    dual_kernel<<<dim3(64, 2), 256>>>(Wc1, Wc1 + DD*DD,
                                      nullptr, bc1,
                                      phi, phjb);

    cls_kernel<<<dim3(16, 16), 256>>>(Wc2, bc2, adj, ew, out);

    if (out_size > NN*NN){
        loss_kernel<<<1, 256>>>(out + NN*NN);
    }
}

// round 16
// speedup vs baseline: 2.6021x; 1.1928x over previous
#include <cuda_runtime.h>

#define NN 1024
#define DD 128
#define NL 3

typedef unsigned long long u64;

// ---------------- f32x2 helpers ----------------
__device__ __forceinline__ u64 pack2(float x, float y){ u64 r; asm("mov.b64 %0,{%1,%2};":"=l"(r):"f"(x),"f"(y)); return r; }
__device__ __forceinline__ u64 dup2(float x){ return pack2(x,x); }
__device__ __forceinline__ u64 fma2(u64 a,u64 b,u64 c){ u64 d; asm("fma.rn.f32x2 %0,%1,%2,%3;":"=l"(d):"l"(a),"l"(b),"l"(c)); return d; }
__device__ __forceinline__ u64 add2(u64 a,u64 b){ u64 d; asm("add.rn.f32x2 %0,%1,%2;":"=l"(d):"l"(a),"l"(b)); return d; }
__device__ __forceinline__ float2 unpk(u64 x){ float2 f; asm("mov.b64 {%0,%1},%2;":"=f"(f.x),"=f"(f.y):"l"(x)); return f; }

// ---------------- scratch ----------------
__device__ float g_h  [NN*DD];
__device__ float g_v  [NN*DD];
__device__ float g_tp [NN*DD];       // tpre = h@Wug + b2   (b2 = bu@Wg1 + bg)
__device__ float g_hi [NN*DD];
__device__ float g_hjb[NN*DD];
__device__ float g_P  [4][NN*DD];    // agg split-K partials
__device__ float g_Wug[NL][DD*DD];
__device__ float g_b2 [NL][DD];
__device__ float g_part[256];

// ---------------- embed: h = nf @ We + be ----------------
__global__ void embed_kernel(const float* __restrict__ nf,
                             const float* __restrict__ We,
                             const float* __restrict__ be) {
    int idx = blockIdx.x * blockDim.x + threadIdx.x;
    int i = idx >> 7, d = idx & 127;
    float a0 = nf[3*i], a1 = nf[3*i+1], a2 = nf[3*i+2];
    g_h[idx] = be[d] + a0*We[d] + a1*We[DD + d] + a2*We[2*DD + d];
}

// ---------------- 16-row x 64-col GEMM core, K=128, double-buffered ----------------
struct SM16 { float As[32][18]; float Bs[32][64]; };

__device__ __forceinline__ void gemm16x64(SM16& s,
    const float* __restrict__ A, int lda,     // tile origin, 16 rows
    const float* __restrict__ B,              // [128][DD] col-slice origin
    u64 acc[2])
{
    int t = threadIdx.x;
    int r0 = (t >> 5) * 2, c0 = (t & 31) * 2;
    int aR = t >> 3, aC = t & 7;              // t<128: A row / float4 idx
    float4 na = make_float4(0,0,0,0), nb0, nb1;
    if (t < 128) na = *(const float4*)&A[(size_t)aR*lda + aC*4];
    nb0 = *(const float4*)&B[(size_t)(t>>4)*DD + (t&15)*4];
    nb1 = *(const float4*)&B[(size_t)((256+t)>>4)*DD + ((256+t)&15)*4];

    for (int kb = 0; kb < 128; kb += 32){
        __syncthreads();
        if (t < 128){
            s.As[aC*4+0][aR]=na.x; s.As[aC*4+1][aR]=na.y;
            s.As[aC*4+2][aR]=na.z; s.As[aC*4+3][aR]=na.w;
        }
        *(float4*)&s.Bs[t>>4][(t&15)*4]         = nb0;
        *(float4*)&s.Bs[(256+t)>>4][((256+t)&15)*4] = nb1;
        __syncthreads();
        if (kb + 32 < 128){
            if (t < 128) na = *(const float4*)&A[(size_t)aR*lda + kb + 32 + aC*4];
            nb0 = *(const float4*)&B[(size_t)(kb+32 + (t>>4))*DD + (t&15)*4];
            nb1 = *(const float4*)&B[(size_t)(kb+32 + ((256+t)>>4))*DD + ((256+t)&15)*4];
        }
#pragma unroll
        for (int k = 0; k < 32; k++){
            float2 a2 = *(const float2*)&s.As[k][r0];
            u64 b = *(const u64*)&s.Bs[k][c0];
            acc[0] = fma2(dup2(a2.x), b, acc[0]);
            acc[1] = fma2(dup2(a2.y), b, acc[1]);
        }
    }
}

__device__ __forceinline__ void store16x64(u64 acc[2], const float* bias, float* O)
{
    int t = threadIdx.x;
    int r0 = (t >> 5) * 2, c0 = (t & 31) * 2;
    u64 bb = 0ull;
    if (bias){ float2 u = *(const float2*)&bias[c0]; bb = pack2(u.x, u.y); }
    *(u64*)&O[(size_t)r0*DD + c0]     = add2(acc[0], bb);
    *(u64*)&O[(size_t)(r0+1)*DD + c0] = add2(acc[1], bb);
}

// ---------------- dual GEMM from g_h: grid (64, 2, 2) ----------------
__global__ __launch_bounds__(256) void dual_kernel(
    const float* __restrict__ B1, const float* __restrict__ B2,
    const float* __restrict__ bias1, const float* __restrict__ bias2,
    float* __restrict__ O1, float* __restrict__ O2)
{
    __shared__ SM16 s;
    int rb = blockIdx.x * 16, cb = blockIdx.y * 64;
    const float* B    = blockIdx.z ? B2    : B1;
    const float* bias = blockIdx.z ? bias2 : bias1;
    float*       O    = blockIdx.z ? O2    : O1;
    u64 acc[2] = {};
    gemm16x64(s, g_h + (size_t)rb*DD, DD, B + cb, acc);
    store16x64(acc, bias ? bias + cb : nullptr, O + (size_t)rb*DD + cb);
}

// ---------------- fold: Wug[l] = Wu[l] @ Wg1[l]. grid (8, 2, NL) ----------------
__global__ __launch_bounds__(256) void fold_kernel(
    const float* __restrict__ Wu, const float* __restrict__ Wg)
{
    __shared__ SM16 s;
    int rb = blockIdx.x * 16, cb = blockIdx.y * 64, l = blockIdx.z;
    u64 acc[2] = {};
    gemm16x64(s, Wu + (size_t)l*DD*DD + rb*DD, DD,
              Wg + (size_t)l*2*DD*DD + cb, acc);
    store16x64(acc, nullptr, g_Wug[l] + (size_t)rb*DD + cb);
}

// ---------------- b2[l] = bu[l]@Wg1[l] + bg[l]. grid NL x 128 ----------------
__global__ void b2_kernel(const float* __restrict__ bu,
                          const float* __restrict__ Wg,
                          const float* __restrict__ bg)
{
    int l = blockIdx.x, t = threadIdx.x;
    float acc = 0.f;
    const float* bl = bu + l*DD;
    const float* w  = Wg + (size_t)l*2*DD*DD;
#pragma unroll 4
    for (int d = 0; d < DD; d++) acc = fmaf(bl[d], w[(size_t)d*DD + t], acc);
    g_b2[l][t] = acc + bg[l*DD + t];
}

// ---------------- agg partials: P[z][:, cb:cb+64] += adj[:, z*256:+256] @ v. grid (32,2,4) ----
__global__ __launch_bounds__(256) void agg_kernel(const float* __restrict__ adj)
{
    __shared__ float As[32][40];     // [k][row], 160B rows: 16B aligned, 2-way stage conflicts
    __shared__ float Bs[32][64];

    int t  = threadIdx.x;
    int rb = blockIdx.x * 32, cb = blockIdx.y * 64, kst = blockIdx.z * 256;
    const float* A = adj + (size_t)rb*NN + kst;
    const float* B = g_v + (size_t)kst*DD + cb;

    int r0 = (t >> 5) * 4, c0 = (t & 31) * 2;
    int aR = t >> 3, aC = t & 7;

    u64 acc[4] = {0ull,0ull,0ull,0ull};

    float4 na = *(const float4*)&A[(size_t)aR*NN + aC*4];
    float4 nb0 = *(const float4*)&B[(size_t)(t>>4)*DD + (t&15)*4];
    float4 nb1 = *(const float4*)&B[(size_t)((256+t)>>4)*DD + ((256+t)&15)*4];

    for (int kb = 0; kb < 256; kb += 32){
        __syncthreads();
        As[aC*4+0][aR]=na.x; As[aC*4+1][aR]=na.y;
        As[aC*4+2][aR]=na.z; As[aC*4+3][aR]=na.w;
        *(float4*)&Bs[t>>4][(t&15)*4]           = nb0;
        *(float4*)&Bs[(256+t)>>4][((256+t)&15)*4] = nb1;
        __syncthreads();
        if (kb + 32 < 256){
            na  = *(const float4*)&A[(size_t)aR*NN + kb + 32 + aC*4];
            nb0 = *(const float4*)&B[(size_t)(kb+32 + (t>>4))*DD + (t&15)*4];
            nb1 = *(const float4*)&B[(size_t)(kb+32 + ((256+t)>>4))*DD + ((256+t)&15)*4];
        }
#pragma unroll
        for (int k = 0; k < 32; k++){
            float4 a = *(const float4*)&As[k][r0];
            u64 b = *(const u64*)&Bs[k][c0];
            acc[0] = fma2(dup2(a.x), b, acc[0]);
            acc[1] = fma2(dup2(a.y), b, acc[1]);
            acc[2] = fma2(dup2(a.z), b, acc[2]);
            acc[3] = fma2(dup2(a.w), b, acc[3]);
        }
    }

    float* P = &g_P[blockIdx.z][(size_t)(rb + r0)*DD + cb + c0];
#pragma unroll
    for (int r = 0; r < 4; r++)
        *(u64*)(P + (size_t)r*DD) = acc[r];
}

// ---------------- gate finish: agg = sum P; t = tpre + agg@Wg2;
//                  h = relu(h + sigmoid(t)*agg).  8r x 64c tiles, grid (128, 2) ----------------
__global__ __launch_bounds__(256) void gatefin_kernel(const float* __restrict__ Wg2)
{
    __shared__ float Ag[8][132];     // summed agg rows (full 128 cols)
    __shared__ float Bs[32][64];

    int t = threadIdx.x;
    int rb = blockIdx.x * 8, cb = blockIdx.y * 64;
    const float* B = Wg2 + cb;

    // slab-sum 4 partials: 8 rows x 128 cols = 256 float4, 1 per thread
    {
        int r = t >> 5, c4 = t & 31;
        size_t off = (size_t)(rb + r)*DD + c4*4;
        float4 p0 = *(const float4*)&g_P[0][off];
        float4 p1 = *(const float4*)&g_P[1][off];
        float4 p2 = *(const float4*)&g_P[2][off];
        float4 p3 = *(const float4*)&g_P[3][off];
        float4 sv;
        sv.x = (p0.x + p1.x) + (p2.x + p3.x);
        sv.y = (p0.y + p1.y) + (p2.y + p3.y);
        sv.z = (p0.z + p1.z) + (p2.z + p3.z);
        sv.w = (p0.w + p1.w) + (p2.w + p3.w);
        *(float4*)&Ag[r][c4*4] = sv;
    }

    float4 nb0 = *(const float4*)&B[(size_t)(t>>4)*DD + (t&15)*4];
    float4 nb1 = *(const float4*)&B[(size_t)((256+t)>>4)*DD + ((256+t)&15)*4];

    int r0 = t >> 5;                 // one row per warp
    int c0 = (t & 31) * 2;
    u64 acc = 0ull;

    for (int kb = 0; kb < 128; kb += 32){
        __syncthreads();             // first pass also covers Ag staging
        *(float4*)&Bs[t>>4][(t&15)*4]           = nb0;
        *(float4*)&Bs[(256+t)>>4][((256+t)&15)*4] = nb1;
        __syncthreads();
        if (kb + 32 < 128){
            nb0 = *(const float4*)&B[(size_t)(kb+32 + (t>>4))*DD + (t&15)*4];
            nb1 = *(const float4*)&B[(size_t)(kb+32 + ((256+t)>>4))*DD + ((256+t)&15)*4];
        }
#pragma unroll
        for (int k = 0; k < 32; k++){
            u64 b = *(const u64*)&Bs[k][c0];
            acc = fma2(dup2(Ag[r0][kb + k]), b, acc);
        }
    }

    // epilogue: t = acc + tpre (b2 already inside tpre — no extra bias)
    {
        size_t off = (size_t)(rb + r0)*DD + cb + c0;
        float2 tp = *(const float2*)&g_tp[off];
        float2 hh = *(const float2*)&g_h[off];
        float2 tv = unpk(acc);
        float ag0 = Ag[r0][cb + c0], ag1 = Ag[r0][cb + c0 + 1];
        float t0 = tv.x + tp.x, t1 = tv.y + tp.y;
        float g0 = 1.f / (1.f + __expf(-t0));
        float g1 = 1.f / (1.f + __expf(-t1));
        float2 o;
        o.x = fmaxf(hh.x + g0*ag0, 0.f);
        o.y = fmaxf(hh.y + g1*ag1, 0.f);
        *(float2*)&g_h[off] = o;
    }
}

// ---------------- classifier + loss partials (64x64 tiles, grid (16,16)) ----------------
__global__ __launch_bounds__(256, 2) void cls_kernel(
    const float* __restrict__ Wc2, const float* __restrict__ bc2,
    const float* __restrict__ adj, const float* __restrict__ ew,
    float* __restrict__ out)
{
    __shared__ float hiS[64][34];
    __shared__ float hjS[64][34];
    __shared__ u64   wsS[64];
    __shared__ float siS[64], sjS[64];
    __shared__ float red[256];

    int t  = threadIdx.x;
    int ib = blockIdx.y * 64, jb = blockIdx.x * 64;

    if (t < 128){
        const float* row = (t < 64) ? &g_hi[(size_t)(ib + t)*DD]
                                    : &g_hjb[(size_t)(jb + t - 64)*DD];
        float s0=0.f,s1=0.f,s2=0.f,s3=0.f;
#pragma unroll
        for (int h = 0; h < DD; h += 4){
            float4 v = *(const float4*)&row[h];
            float4 w = *(const float4*)&Wc2[h];
            s0=fmaf(v.x,w.x,s0); s1=fmaf(v.y,w.y,s1);
            s2=fmaf(v.z,w.z,s2); s3=fmaf(v.w,w.w,s3);
        }
        float s = 0.5f*((s0+s1)+(s2+s3));
        if (t < 64) siS[t]      = s;
        else        sjS[t - 64] = s + bc2[0];
    } else if (t < 192){
        int h2 = t - 128;
        wsS[h2] = pack2(0.5f*Wc2[2*h2], 0.5f*Wc2[2*h2+1]);
    }

    int ig = t >> 4, jg = t & 15;
    const u64 amask = 0x7FFFFFFF7FFFFFFFull;

    // prefetch chunk 0
    float2 phi[4], phj[4];
#pragma unroll
    for (int e = 0; e < 4; e++){
        int idx = e*256 + t;
        int r = idx >> 4, q = (idx & 15) * 2;
        phi[e] = *(const float2*)&g_hi [(size_t)(ib+r)*DD + q];
        phj[e] = *(const float2*)&g_hjb[(size_t)(jb+r)*DD + q];
    }

    u64 acc[4][4];
#pragma unroll
    for (int a=0;a<4;a++)
#pragma unroll
        for (int b=0;b<4;b++) acc[a][b]=0ull;

    for (int hc = 0; hc < DD; hc += 32){
        __syncthreads();
#pragma unroll
        for (int e=0;e<4;e++){
            int idx=e*256+t;
            int r=idx>>4, q=(idx&15)*2;
            *(float2*)&hiS[r][q] = phi[e];
            *(float2*)&hjS[r][q] = phj[e];
        }
        __syncthreads();
        if (hc + 32 < DD){
#pragma unroll
            for (int e=0;e<4;e++){
                int idx=e*256+t;
                int r=idx>>4, q=(idx&15)*2;
                phi[e] = *(const float2*)&g_hi [(size_t)(ib+r)*DD + hc + 32 + q];
                phj[e] = *(const float2*)&g_hjb[(size_t)(jb+r)*DD + hc + 32 + q];
            }
        }
#pragma unroll
        for (int hp=0; hp<16; hp++){
            u64 wp = wsS[(hc>>1)+hp];
            u64 ai[4], bj[4];
#pragma unroll
            for (int a=0;a<4;a++){
                ai[a] = *(const u64*)&hiS[ig + a*16][hp*2];
                bj[a] = *(const u64*)&hjS[jg + a*16][hp*2];
            }
#pragma unroll
            for (int a=0;a<4;a++)
#pragma unroll
                for (int b=0;b<4;b++){
                    u64 s = add2(ai[a], bj[b]) & amask;
                    acc[a][b] = fma2(s, wp, acc[a][b]);
                }
        }
    }

    float lsum = 0.f;
#pragma unroll
    for (int a=0;a<4;a++){
        int i = ib + ig + a*16;
        float sia = siS[ig + a*16];
#pragma unroll
        for (int b=0;b<4;b++){
            int j = jb + jg + b*16;
            float2 p = unpk(acc[a][b]);
            float lg = (p.x + p.y) + sia + sjS[jg + b*16];
            size_t off = (size_t)i*NN + j;
            out[off] = lg;
            float d = lg*adj[off] - ew[off];
            lsum = fmaf(d, d, lsum);
        }
    }

    red[t] = lsum;
    __syncthreads();
#pragma unroll
    for (int s=128; s>0; s>>=1){
        if (t < s) red[t] += red[t+s];
        __syncthreads();
    }
    if (t == 0) g_part[blockIdx.y*16 + blockIdx.x] = red[0];
}

// ---------------- final loss reduce ----------------
__global__ void loss_kernel(float* __restrict__ out_loss){
    __shared__ float red[256];
    int t = threadIdx.x;
    red[t] = g_part[t];
    __syncthreads();
#pragma unroll
    for (int s=128; s>0; s>>=1){
        if (t < s) red[t] += red[t+s];
        __syncthreads();
    }
    if (t == 0) out_loss[0] = red[0] * (1.f/(1024.f*1024.f));
}

// ---------------- launch ----------------
extern "C" void kernel_launch(void* const* d_in, const int* in_sizes, int n_in,
                              void* d_out, int out_size)
{
    const float* nf   = (const float*)d_in[0];
    const float* adj  = (const float*)d_in[1];
    const float* ew   = (const float*)d_in[2];
    const float* We   = (const float*)d_in[3];
    const float* be   = (const float*)d_in[4];
    const float* Wu   = (const float*)d_in[5];
    const float* bu   = (const float*)d_in[6];
    const float* Wv   = (const float*)d_in[7];
    const float* bv   = (const float*)d_in[8];
    const float* Wg   = (const float*)d_in[9];
    const float* bg   = (const float*)d_in[10];
    const float* Wc1  = (const float*)d_in[11];
    const float* bc1  = (const float*)d_in[12];
    const float* Wc2  = (const float*)d_in[13];
    const float* bc2  = (const float*)d_in[14];
    float* out = (float*)d_out;

    float *pv, *ptp, *phi, *phjb, *pWug, *pb2;
    cudaGetSymbolAddress((void**)&pv,   g_v);
    cudaGetSymbolAddress((void**)&ptp,  g_tp);
    cudaGetSymbolAddress((void**)&phi,  g_hi);
    cudaGetSymbolAddress((void**)&phjb, g_hjb);
    cudaGetSymbolAddress((void**)&pWug, g_Wug);
    cudaGetSymbolAddress((void**)&pb2,  g_b2);

    embed_kernel<<<NN*DD/256, 256>>>(nf, We, be);
    fold_kernel<<<dim3(8, 2, NL), 256>>>(Wu, Wg);
    b2_kernel<<<NL, DD>>>(bu, Wg, bg);

    for (int l = 0; l < NL; l++){
        // v = h@Wv + bv ; tpre = h@Wug + b2
        dual_kernel<<<dim3(64, 2, 2), 256>>>(Wv + (size_t)l*DD*DD, pWug + (size_t)l*DD*DD,
                                             bv + l*DD, pb2 + l*DD,
                                             pv, ptp);
        agg_kernel<<<dim3(32, 2, 4), 256>>>(adj);
        gatefin_kernel<<<dim3(128, 2), 256>>>(Wg + (size_t)l*2*DD*DD + DD*DD);
    }

    // hi = h@Wc1[:D] ; hjb = h@Wc1[D:] + bc1
    dual_kernel<<<dim3(64, 2, 2), 256>>>(Wc1, Wc1 + DD*DD,
                                         nullptr, bc1,
                                         phi, phjb);

    cls_kernel<<<dim3(16, 16), 256>>>(Wc2, bc2, adj, ew, out);

    if (out_size > NN*NN){
        loss_kernel<<<1, 256>>>(out + NN*NN);
    }
}

// round 17
// speedup vs baseline: 2.6949x; 1.0356x over previous
#include <cuda_runtime.h>

#define NN 1024
#define DD 128
#define NL 3

typedef unsigned long long u64;

// ---------------- f32x2 helpers ----------------
__device__ __forceinline__ u64 pack2(float x, float y){ u64 r; asm("mov.b64 %0,{%1,%2};":"=l"(r):"f"(x),"f"(y)); return r; }
__device__ __forceinline__ u64 dup2(float x){ return pack2(x,x); }
__device__ __forceinline__ u64 fma2(u64 a,u64 b,u64 c){ u64 d; asm("fma.rn.f32x2 %0,%1,%2,%3;":"=l"(d):"l"(a),"l"(b),"l"(c)); return d; }
__device__ __forceinline__ u64 add2(u64 a,u64 b){ u64 d; asm("add.rn.f32x2 %0,%1,%2;":"=l"(d):"l"(a),"l"(b)); return d; }
__device__ __forceinline__ float2 unpk(u64 x){ float2 f; asm("mov.b64 {%0,%1},%2;":"=f"(f.x),"=f"(f.y):"l"(x)); return f; }

// ---------------- scratch ----------------
__device__ float g_h  [NN*DD];
__device__ float g_hB [NN*DD];       // double buffer for h
__device__ float g_hi [NN*DD];
__device__ float g_hjb[NN*DD];
__device__ float g_P  [8][NN*DD];    // S split-K partials
__device__ float g_Wug[NL][DD*DD];   // Wu@Wg1
__device__ float g_Wvg[NL][DD*DD];   // Wv@Wg2
__device__ float g_b2 [NL][DD];      // bu@Wg1 + bg
__device__ float g_c2 [NL][DD];      // bv@Wg2
__device__ float g_rs [NN];          // adj row sums
__device__ float g_part[256];

// ---------------- 16-row x 64-col GEMM core, K=128, double-buffered ----------------
struct SM16 { float As[32][18]; float Bs[32][64]; };

__device__ __forceinline__ void gemm16x64(SM16& s,
    const float* __restrict__ A, int lda,     // tile origin, 16 rows
    const float* __restrict__ B,              // [128][DD] col-slice origin
    u64 acc[2])
{
    int t = threadIdx.x;
    int r0 = (t >> 5) * 2, c0 = (t & 31) * 2;
    int aR = t >> 3, aC = t & 7;
    float4 na = make_float4(0,0,0,0), nb0, nb1;
    if (t < 128) na = *(const float4*)&A[(size_t)aR*lda + aC*4];
    nb0 = *(const float4*)&B[(size_t)(t>>4)*DD + (t&15)*4];
    nb1 = *(const float4*)&B[(size_t)((256+t)>>4)*DD + ((256+t)&15)*4];

    for (int kb = 0; kb < 128; kb += 32){
        __syncthreads();
        if (t < 128){
            s.As[aC*4+0][aR]=na.x; s.As[aC*4+1][aR]=na.y;
            s.As[aC*4+2][aR]=na.z; s.As[aC*4+3][aR]=na.w;
        }
        *(float4*)&s.Bs[t>>4][(t&15)*4]           = nb0;
        *(float4*)&s.Bs[(256+t)>>4][((256+t)&15)*4] = nb1;
        __syncthreads();
        if (kb + 32 < 128){
            if (t < 128) na = *(const float4*)&A[(size_t)aR*lda + kb + 32 + aC*4];
            nb0 = *(const float4*)&B[(size_t)(kb+32 + (t>>4))*DD + (t&15)*4];
            nb1 = *(const float4*)&B[(size_t)(kb+32 + ((256+t)>>4))*DD + ((256+t)&15)*4];
        }
#pragma unroll
        for (int k = 0; k < 32; k++){
            float2 a2 = *(const float2*)&s.As[k][r0];
            u64 b = *(const u64*)&s.Bs[k][c0];
            acc[0] = fma2(dup2(a2.x), b, acc[0]);
            acc[1] = fma2(dup2(a2.y), b, acc[1]);
        }
    }
}

__device__ __forceinline__ void store16x64(u64 acc[2], const float* bias, float* O)
{
    int t = threadIdx.x;
    int r0 = (t >> 5) * 2, c0 = (t & 31) * 2;
    u64 bb = 0ull;
    if (bias){ float2 u = *(const float2*)&bias[c0]; bb = pack2(u.x, u.y); }
    *(u64*)&O[(size_t)r0*DD + c0]     = add2(acc[0], bb);
    *(u64*)&O[(size_t)(r0+1)*DD + c0] = add2(acc[1], bb);
}

// ---------------- init: embed + folds + b2/c2 + rowsums, one launch ----------------
// grid 195: [0,48) fold Wug, [48,96) fold Wvg, [96,99) b2c2, [99,131) rs, [131,195) embed
__global__ __launch_bounds__(256) void init_kernel(
    const float* __restrict__ nf, const float* __restrict__ adj,
    const float* __restrict__ We, const float* __restrict__ be,
    const float* __restrict__ Wu, const float* __restrict__ Wv,
    const float* __restrict__ Wg, const float* __restrict__ bu,
    const float* __restrict__ bv, const float* __restrict__ bg)
{
    __shared__ SM16 s;
    int b = blockIdx.x, t = threadIdx.x;

    if (b < 96){
        int fb = (b < 48) ? b : b - 48;
        int l = fb / 16, tile = fb % 16;
        int rb = (tile >> 1) * 16, cb = (tile & 1) * 64;
        u64 acc[2] = {};
        if (b < 48){
            gemm16x64(s, Wu + (size_t)l*DD*DD + rb*DD, DD,
                      Wg + (size_t)l*2*DD*DD + cb, acc);
            store16x64(acc, nullptr, g_Wug[l] + (size_t)rb*DD + cb);
        } else {
            gemm16x64(s, Wv + (size_t)l*DD*DD + rb*DD, DD,
                      Wg + (size_t)l*2*DD*DD + DD*DD + cb, acc);
            store16x64(acc, nullptr, g_Wvg[l] + (size_t)rb*DD + cb);
        }
    } else if (b < 99){
        int l = b - 96;
        if (t < DD){
            float acc = 0.f;
            const float* bl = bu + l*DD;
            const float* w  = Wg + (size_t)l*2*DD*DD;          // Wg1
#pragma unroll 4
            for (int d = 0; d < DD; d++) acc = fmaf(bl[d], w[(size_t)d*DD + t], acc);
            g_b2[l][t] = acc + bg[l*DD + t];
        } else {
            int j = t - DD;
            float acc = 0.f;
            const float* bl = bv + l*DD;
            const float* w  = Wg + (size_t)l*2*DD*DD + DD*DD;  // Wg2
#pragma unroll 4
            for (int d = 0; d < DD; d++) acc = fmaf(bl[d], w[(size_t)d*DD + j], acc);
            g_c2[l][j] = acc;
        }
    } else if (b < 131){
        int row = (b - 99)*32 + (t >> 3);
        int l8 = t & 7;
        float sum = 0.f;
#pragma unroll 8
        for (int i = 0; i < 32; i++){
            float4 v = *(const float4*)&adj[(size_t)row*NN + (size_t)(l8 + 8*i)*4];
            sum += (v.x + v.y) + (v.z + v.w);
        }
#pragma unroll
        for (int o = 4; o > 0; o >>= 1)
            sum += __shfl_down_sync(0xffffffffu, sum, o);
        if (l8 == 0) g_rs[row] = sum;
    } else {
        int idx0 = (b - 131)*2048 + t;
#pragma unroll
        for (int e = 0; e < 8; e++){
            int idx = idx0 + e*256;
            int i = idx >> 7, d = idx & 127;
            float a0 = nf[3*i], a1 = nf[3*i+1], a2 = nf[3*i+2];
            g_h[idx] = be[d] + a0*We[d] + a1*We[DD + d] + a2*We[2*DD + d];
        }
    }
}

// ---------------- S partials: P[z][:, cb:+64] = adj[:, z*128:+128] @ h. grid (32,2,8) ----
__global__ __launch_bounds__(256) void S_kernel(const float* __restrict__ adj,
                                                const float* __restrict__ h)
{
    __shared__ float As[32][40];
    __shared__ float Bs[32][64];

    int t  = threadIdx.x;
    int rb = blockIdx.x * 32, cb = blockIdx.y * 64, kst = blockIdx.z * 128;
    const float* A = adj + (size_t)rb*NN + kst;
    const float* B = h + (size_t)kst*DD + cb;

    int r0 = (t >> 5) * 4, c0 = (t & 31) * 2;
    int aR = t >> 3, aC = t & 7;

    u64 acc[4] = {0ull,0ull,0ull,0ull};

    float4 na  = *(const float4*)&A[(size_t)aR*NN + aC*4];
    float4 nb0 = *(const float4*)&B[(size_t)(t>>4)*DD + (t&15)*4];
    float4 nb1 = *(const float4*)&B[(size_t)((256+t)>>4)*DD + ((256+t)&15)*4];

    for (int kb = 0; kb < 128; kb += 32){
        __syncthreads();
        As[aC*4+0][aR]=na.x; As[aC*4+1][aR]=na.y;
        As[aC*4+2][aR]=na.z; As[aC*4+3][aR]=na.w;
        *(float4*)&Bs[t>>4][(t&15)*4]           = nb0;
        *(float4*)&Bs[(256+t)>>4][((256+t)&15)*4] = nb1;
        __syncthreads();
        if (kb + 32 < 128){
            na  = *(const float4*)&A[(size_t)aR*NN + kb + 32 + aC*4];
            nb0 = *(const float4*)&B[(size_t)(kb+32 + (t>>4))*DD + (t&15)*4];
            nb1 = *(const float4*)&B[(size_t)(kb+32 + ((256+t)>>4))*DD + ((256+t)&15)*4];
        }
#pragma unroll
        for (int k = 0; k < 32; k++){
            float4 a = *(const float4*)&As[k][r0];
            u64 b = *(const u64*)&Bs[k][c0];
            acc[0] = fma2(dup2(a.x), b, acc[0]);
            acc[1] = fma2(dup2(a.y), b, acc[1]);
            acc[2] = fma2(dup2(a.z), b, acc[2]);
            acc[3] = fma2(dup2(a.w), b, acc[3]);
        }
    }

    float* P = &g_P[blockIdx.z][(size_t)(rb + r0)*DD + cb + c0];
#pragma unroll
    for (int r = 0; r < 4; r++)
        *(u64*)(P + (size_t)r*DD) = acc[r];
}

// ---------------- megafin: S = sum P; t = h@Wug + S@Wvg + b2 + rs*c2;
//   agg = S@Wv + rs*bv; h_new = relu(h + sigmoid(t)*agg). 8r x 64c, grid (128,2) ----------
__global__ __launch_bounds__(256) void megafin_kernel(
    const float* __restrict__ Wv,   const float* __restrict__ Wug,
    const float* __restrict__ Wvg,  const float* __restrict__ b2,
    const float* __restrict__ c2,   const float* __restrict__ bv,
    const float* __restrict__ hsrc, float* __restrict__ hdst)
{
    __shared__ float hS[8][132];
    __shared__ float sS[8][132];
    __shared__ float Bs[3][32][64];

    int t = threadIdx.x;
    int rb = blockIdx.x * 8, cb = blockIdx.y * 64;

    // stage h rows (full 128 cols)
    {
        int r = t >> 5, c4 = t & 31;
        *(float4*)&hS[r][c4*4] =
            *(const float4*)&hsrc[(size_t)(rb + r)*DD + c4*4];
    }
    // stage summed S rows
    {
        int r = t >> 5, c4 = t & 31;
        size_t off = (size_t)(rb + r)*DD + c4*4;
        float4 s0 = *(const float4*)&g_P[0][off];
#pragma unroll
        for (int z = 1; z < 8; z++){
            float4 p = *(const float4*)&g_P[z][off];
            s0.x += p.x; s0.y += p.y; s0.z += p.z; s0.w += p.w;
        }
        *(float4*)&sS[r][c4*4] = s0;
    }

    const float* Wm0 = Wug;
    const float* Wm1 = Wvg;
    const float* Wm2 = Wv;

    // prefetch chunk 0: 3 x 32k x 64c = 1536 float4
    float4 nb[6];
#pragma unroll
    for (int e = 0; e < 6; e++){
        int idx = e*256 + t;
        int m = idx >> 9, k = (idx >> 4) & 31, c4 = idx & 15;
        const float* W = (m == 0) ? Wm0 : (m == 1) ? Wm1 : Wm2;
        nb[e] = *(const float4*)&W[(size_t)k*DD + cb + c4*4];
    }

    int r0 = t >> 5;              // one row per warp
    int c0 = (t & 31) * 2;
    u64 acc_t = 0ull, acc_g = 0ull;

    for (int kb = 0; kb < 128; kb += 32){
        __syncthreads();          // first pass also covers hS/sS staging
#pragma unroll
        for (int e = 0; e < 6; e++){
            int idx = e*256 + t;
            int m = idx >> 9, k = (idx >> 4) & 31, c4 = idx & 15;
            *(float4*)&Bs[m][k][c4*4] = nb[e];
        }
        __syncthreads();
        if (kb + 32 < 128){
#pragma unroll
            for (int e = 0; e < 6; e++){
                int idx = e*256 + t;
                int m = idx >> 9, k = (idx >> 4) & 31, c4 = idx & 15;
                const float* W = (m == 0) ? Wm0 : (m == 1) ? Wm1 : Wm2;
                nb[e] = *(const float4*)&W[(size_t)(kb + 32 + k)*DD + cb + c4*4];
            }
        }
#pragma unroll
        for (int k = 0; k < 32; k++){
            u64 ah = dup2(hS[r0][kb + k]);
            u64 as = dup2(sS[r0][kb + k]);
            u64 b0 = *(const u64*)&Bs[0][k][c0];
            u64 b1 = *(const u64*)&Bs[1][k][c0];
            u64 b2_ = *(const u64*)&Bs[2][k][c0];
            acc_t = fma2(ah, b0, acc_t);
            acc_t = fma2(as, b1, acc_t);
            acc_g = fma2(as, b2_, acc_g);
        }
    }

    // epilogue
    {
        int row = rb + r0;
        float rsv = g_rs[row];
        float2 tv  = unpk(acc_t);
        float2 gv  = unpk(acc_g);
        float2 b2v = *(const float2*)&b2[cb + c0];
        float2 c2v = *(const float2*)&c2[cb + c0];
        float2 bvv = *(const float2*)&bv[cb + c0];
        float t0 = tv.x + b2v.x + rsv * c2v.x;
        float t1 = tv.y + b2v.y + rsv * c2v.y;
        float a0 = gv.x + rsv * bvv.x;
        float a1 = gv.y + rsv * bvv.y;
        float h0 = hS[r0][cb + c0], h1 = hS[r0][cb + c0 + 1];
        float s0 = 1.f/(1.f + __expf(-t0));
        float s1 = 1.f/(1.f + __expf(-t1));
        float o0 = fmaxf(h0 + s0*a0, 0.f);
        float o1 = fmaxf(h1 + s1*a1, 0.f);
        *(float2*)&hdst[(size_t)row*DD + cb + c0] = make_float2(o0, o1);
    }
}

// ---------------- dual GEMM (classifier): grid (64, 2, 2) ----------------
__global__ __launch_bounds__(256) void dual_kernel(
    const float* __restrict__ h,
    const float* __restrict__ B1, const float* __restrict__ B2,
    const float* __restrict__ bias1, const float* __restrict__ bias2,
    float* __restrict__ O1, float* __restrict__ O2)
{
    __shared__ SM16 s;
    int rb = blockIdx.x * 16, cb = blockIdx.y * 64;
    const float* B    = blockIdx.z ? B2    : B1;
    const float* bias = blockIdx.z ? bias2 : bias1;
    float*       O    = blockIdx.z ? O2    : O1;
    u64 acc[2] = {};
    gemm16x64(s, h + (size_t)rb*DD, DD, B + cb, acc);
    store16x64(acc, bias ? bias + cb : nullptr, O + (size_t)rb*DD + cb);
}

// ---------------- classifier + loss partials (64x64 tiles, grid (16,16)) ----------------
__global__ __launch_bounds__(256, 2) void cls_kernel(
    const float* __restrict__ Wc2, const float* __restrict__ bc2,
    const float* __restrict__ adj, const float* __restrict__ ew,
    float* __restrict__ out)
{
    __shared__ float hiS[64][34];
    __shared__ float hjS[64][34];
    __shared__ u64   wsS[64];
    __shared__ float siS[64], sjS[64];
    __shared__ float red[256];

    int t  = threadIdx.x;
    int ib = blockIdx.y * 64, jb = blockIdx.x * 64;

    if (t < 128){
        const float* row = (t < 64) ? &g_hi[(size_t)(ib + t)*DD]
                                    : &g_hjb[(size_t)(jb + t - 64)*DD];
        float s0=0.f,s1=0.f,s2=0.f,s3=0.f;
#pragma unroll
        for (int h = 0; h < DD; h += 4){
            float4 v = *(const float4*)&row[h];
            float4 w = *(const float4*)&Wc2[h];
            s0=fmaf(v.x,w.x,s0); s1=fmaf(v.y,w.y,s1);
            s2=fmaf(v.z,w.z,s2); s3=fmaf(v.w,w.w,s3);
        }
        float s = 0.5f*((s0+s1)+(s2+s3));
        if (t < 64) siS[t]      = s;
        else        sjS[t - 64] = s + bc2[0];
    } else if (t < 192){
        int h2 = t - 128;
        wsS[h2] = pack2(0.5f*Wc2[2*h2], 0.5f*Wc2[2*h2+1]);
    }

    int ig = t >> 4, jg = t & 15;
    const u64 amask = 0x7FFFFFFF7FFFFFFFull;

    float2 phi[4], phj[4];
#pragma unroll
    for (int e = 0; e < 4; e++){
        int idx = e*256 + t;
        int r = idx >> 4, q = (idx & 15) * 2;
        phi[e] = *(const float2*)&g_hi [(size_t)(ib+r)*DD + q];
        phj[e] = *(const float2*)&g_hjb[(size_t)(jb+r)*DD + q];
    }

    u64 acc[4][4];
#pragma unroll
    for (int a=0;a<4;a++)
#pragma unroll
        for (int b=0;b<4;b++) acc[a][b]=0ull;

    for (int hc = 0; hc < DD; hc += 32){
        __syncthreads();
#pragma unroll
        for (int e=0;e<4;e++){
            int idx=e*256+t;
            int r=idx>>4, q=(idx&15)*2;
            *(float2*)&hiS[r][q] = phi[e];
            *(float2*)&hjS[r][q] = phj[e];
        }
        __syncthreads();
        if (hc + 32 < DD){
#pragma unroll
            for (int e=0;e<4;e++){
                int idx=e*256+t;
                int r=idx>>4, q=(idx&15)*2;
                phi[e] = *(const float2*)&g_hi [(size_t)(ib+r)*DD + hc + 32 + q];
                phj[e] = *(const float2*)&g_hjb[(size_t)(jb+r)*DD + hc + 32 + q];
            }
        }
#pragma unroll
        for (int hp=0; hp<16; hp++){
            u64 wp = wsS[(hc>>1)+hp];
            u64 ai[4], bj[4];
#pragma unroll
            for (int a=0;a<4;a++){
                ai[a] = *(const u64*)&hiS[ig + a*16][hp*2];
                bj[a] = *(const u64*)&hjS[jg + a*16][hp*2];
            }
#pragma unroll
            for (int a=0;a<4;a++)
#pragma unroll
                for (int b=0;b<4;b++){
                    u64 s = add2(ai[a], bj[b]) & amask;
                    acc[a][b] = fma2(s, wp, acc[a][b]);
                }
        }
    }

    float lsum = 0.f;
#pragma unroll
    for (int a=0;a<4;a++){
        int i = ib + ig + a*16;
        float sia = siS[ig + a*16];
#pragma unroll
        for (int b=0;b<4;b++){
            int j = jb + jg + b*16;
            float2 p = unpk(acc[a][b]);
            float lg = (p.x + p.y) + sia + sjS[jg + b*16];
            size_t off = (size_t)i*NN + j;
            out[off] = lg;
            float d = lg*adj[off] - ew[off];
            lsum = fmaf(d, d, lsum);
        }
    }

    red[t] = lsum;
    __syncthreads();
#pragma unroll
    for (int s=128; s>0; s>>=1){
        if (t < s) red[t] += red[t+s];
        __syncthreads();
    }
    if (t == 0) g_part[blockIdx.y*16 + blockIdx.x] = red[0];
}

// ---------------- final loss reduce ----------------
__global__ void loss_kernel(float* __restrict__ out_loss){
    __shared__ float red[256];
    int t = threadIdx.x;
    red[t] = g_part[t];
    __syncthreads();
#pragma unroll
    for (int s=128; s>0; s>>=1){
        if (t < s) red[t] += red[t+s];
        __syncthreads();
    }
    if (t == 0) out_loss[0] = red[0] * (1.f/(1024.f*1024.f));
}

// ---------------- launch ----------------
extern "C" void kernel_launch(void* const* d_in, const int* in_sizes, int n_in,
                              void* d_out, int out_size)
{
    const float* nf   = (const float*)d_in[0];
    const float* adj  = (const float*)d_in[1];
    const float* ew   = (const float*)d_in[2];
    const float* We   = (const float*)d_in[3];
    const float* be   = (const float*)d_in[4];
    const float* Wu   = (const float*)d_in[5];
    const float* bu   = (const float*)d_in[6];
    const float* Wv   = (const float*)d_in[7];
    const float* bv   = (const float*)d_in[8];
    const float* Wg   = (const float*)d_in[9];
    const float* bg   = (const float*)d_in[10];
    const float* Wc1  = (const float*)d_in[11];
    const float* bc1  = (const float*)d_in[12];
    const float* Wc2  = (const float*)d_in[13];
    const float* bc2  = (const float*)d_in[14];
    float* out = (float*)d_out;

    float *ph, *phB, *phi, *phjb, *pWug, *pWvg, *pb2, *pc2;
    cudaGetSymbolAddress((void**)&ph,   g_h);
    cudaGetSymbolAddress((void**)&phB,  g_hB);
    cudaGetSymbolAddress((void**)&phi,  g_hi);
    cudaGetSymbolAddress((void**)&phjb, g_hjb);
    cudaGetSymbolAddress((void**)&pWug, g_Wug);
    cudaGetSymbolAddress((void**)&pWvg, g_Wvg);
    cudaGetSymbolAddress((void**)&pb2,  g_b2);
    cudaGetSymbolAddress((void**)&pc2,  g_c2);

    init_kernel<<<195, 256>>>(nf, adj, We, be, Wu, Wv, Wg, bu, bv, bg);

    const float* hsrc = ph;
    float*       hdst = phB;
    for (int l = 0; l < NL; l++){
        S_kernel<<<dim3(32, 2, 8), 256>>>(adj, hsrc);
        megafin_kernel<<<dim3(128, 2), 256>>>(Wv + (size_t)l*DD*DD,
                                              pWug + (size_t)l*DD*DD,
                                              pWvg + (size_t)l*DD*DD,
                                              pb2 + l*DD, pc2 + l*DD,
                                              bv + l*DD,
                                              hsrc, hdst);
        const float* tmp = hsrc; hsrc = hdst; hdst = (float*)tmp;
    }

    // hi = h@Wc1[:D] ; hjb = h@Wc1[D:] + bc1
    dual_kernel<<<dim3(64, 2, 2), 256>>>(hsrc, Wc1, Wc1 + DD*DD,
                                         nullptr, bc1,
                                         phi, phjb);

    cls_kernel<<<dim3(16, 16), 256>>>(Wc2, bc2, adj, ew, out);

    if (out_size > NN*NN){
        loss_kernel<<<1, 256>>>(out + NN*NN);
    }
}